// round 3
// baseline (speedup 1.0000x reference)
#include <cuda_runtime.h>
#include <cuda_bf16.h>
#include <cstdint>

#define N_NODES 100000
#define D 128

// Scratch: neighbor-sum accumulator (51.2 MB), static device global.
__device__ float g_neigh[(size_t)N_NODES * D];

// ---------------------------------------------------------------------------
// packed f32x2 helpers (base Blackwell PTX; no 'a' feature needed)
// ---------------------------------------------------------------------------
__device__ __forceinline__ unsigned long long pk2(float lo, float hi) {
    unsigned long long r;
    asm("mov.b64 %0, {%1, %2};" : "=l"(r) : "f"(lo), "f"(hi));
    return r;
}
__device__ __forceinline__ void upk2(unsigned long long v, float& lo, float& hi) {
    asm("mov.b64 {%0, %1}, %2;" : "=f"(lo), "=f"(hi) : "l"(v));
}
__device__ __forceinline__ unsigned long long fma2(unsigned long long a,
                                                   unsigned long long b,
                                                   unsigned long long c) {
    unsigned long long d;
    asm("fma.rn.f32x2 %0, %1, %2, %3;" : "=l"(d) : "l"(a), "l"(b), "l"(c));
    return d;
}
__device__ __forceinline__ uint32_t smem_u32(const void* p) {
    uint32_t a;
    asm("{ .reg .u64 t; cvta.to.shared.u64 t, %1; cvt.u32.u64 %0, t; }" : "=r"(a) : "l"(p));
    return a;
}

// ---------------------------------------------------------------------------
// Kernel 1: g_neigh = (1+eps)*feat   (self term folded into accumulator init)
// ---------------------------------------------------------------------------
__global__ void init_neigh_kernel(const float* __restrict__ feat,
                                  const float* __restrict__ epsp) {
    const float e1 = 1.0f + epsp[0];
    size_t total4 = (size_t)N_NODES * D / 4;
    size_t stride = (size_t)gridDim.x * blockDim.x;
    for (size_t i = (size_t)blockIdx.x * blockDim.x + threadIdx.x; i < total4; i += stride) {
        float4 v = reinterpret_cast<const float4*>(feat)[i];
        v.x *= e1; v.y *= e1; v.z *= e1; v.w *= e1;
        reinterpret_cast<float4*>(g_neigh)[i] = v;
    }
}

// ---------------------------------------------------------------------------
// Kernel 2: edge scatter. Warp per edge: float4 gather + red.global.add.v4.
// ---------------------------------------------------------------------------
__global__ void scatter_kernel(const float* __restrict__ feat,
                               const int* __restrict__ src,
                               const int* __restrict__ dst,
                               int n_edges) {
    long long total = (long long)n_edges * 32;
    long long stride = (long long)gridDim.x * blockDim.x;
    for (long long i = (long long)blockIdx.x * blockDim.x + threadIdx.x;
         i < total; i += stride) {
        int e    = (int)(i >> 5);
        int lane = (int)(i & 31);
        int s = src[e];
        int d = dst[e];
        float4 v = *reinterpret_cast<const float4*>(feat + (size_t)s * D + lane * 4);
        float* p = g_neigh + (size_t)d * D + lane * 4;
        asm volatile("red.global.add.v4.f32 [%0], {%1,%2,%3,%4};"
                     :: "l"(p), "f"(v.x), "f"(v.y), "f"(v.z), "f"(v.w)
                     : "memory");
    }
}

// ---------------------------------------------------------------------------
// Kernel 3: fused MLP with packed f32x2 FMA.
// Per CTA: 128 rows. 256 threads, each owns a 4-row x 16-col micro-tile
// (acc as 32 packed f32x2). Weights staged in smem row-major, loaded as
// ld.shared.v2.b64 (pre-packed operand pairs).
// ---------------------------------------------------------------------------
#define TILE_M   128
#define H_STRIDE 132
#define MLP_THREADS 256

// smem floats: W1 [0,16384) | W2 [16384,32768) | h [32768, 32768+128*132)
#define SMEM_FLOATS (128*128 + 128*128 + TILE_M*H_STRIDE)

__global__ __launch_bounds__(MLP_THREADS, 1)
void mlp_kernel(const float* __restrict__ W1,
                const float* __restrict__ b1,
                const float* __restrict__ W2,
                const float* __restrict__ b2,
                float* __restrict__ out) {
    extern __shared__ float smem[];
    float* sW1 = smem;
    float* sW2 = smem + 128 * 128;
    float* sh  = smem + 2 * 128 * 128;

    const int tid = threadIdx.x;
    const int tm  = tid >> 3;           // 0..31
    const int tn  = tid & 7;            // 0..7
    const int m0  = tm * 4;             // 4 rows
    const int n0  = tn * 16;            // 16 cols
    const int row_base = blockIdx.x * TILE_M;

    // Stage W1 / W2 (float4 linear)
    {
        const float4* gW1 = reinterpret_cast<const float4*>(W1);
        const float4* gW2 = reinterpret_cast<const float4*>(W2);
        float4* s1 = reinterpret_cast<float4*>(sW1);
        float4* s2 = reinterpret_cast<float4*>(sW2);
        for (int i = tid; i < 128 * 128 / 4; i += MLP_THREADS) {
            s1[i] = gW1[i];
            s2[i] = gW2[i];
        }
    }

    // Stage h tile from g_neigh (eps-scaled feat already folded in)
    for (int i = tid; i < TILE_M * 32; i += MLP_THREADS) {
        int r  = i >> 5;
        int c4 = i & 31;
        int m  = row_base + r;
        float4 v = (m < N_NODES)
                   ? *reinterpret_cast<const float4*>(g_neigh + (size_t)m * D + c4 * 4)
                   : make_float4(0.f, 0.f, 0.f, 0.f);
        *reinterpret_cast<float4*>(sh + r * H_STRIDE + c4 * 4) = v;
    }
    __syncthreads();

    // shared-address bases (u32 shared window)
    const uint32_t sh_u  = smem_u32(sh);
    const uint32_t w1_u  = smem_u32(sW1) + n0 * 4;
    const uint32_t w2_u  = smem_u32(sW2) + n0 * 4;

    unsigned long long acc[4][8];

    // ================= GEMM 1: t = relu(h @ W1 + b1) =================
#pragma unroll
    for (int i = 0; i < 4; i++)
#pragma unroll
        for (int j = 0; j < 8; j++) acc[i][j] = 0ULL;

    {
        uint32_t a_addr = sh_u + (uint32_t)(m0 * H_STRIDE) * 4;
        uint32_t w_addr = w1_u;
#pragma unroll 4
        for (int k = 0; k < 128; k++) {
            float a0, a1, a2, a3;
            asm("ld.shared.f32 %0, [%1];" : "=f"(a0) : "r"(a_addr));
            asm("ld.shared.f32 %0, [%1];" : "=f"(a1) : "r"(a_addr + 528));
            asm("ld.shared.f32 %0, [%1];" : "=f"(a2) : "r"(a_addr + 1056));
            asm("ld.shared.f32 %0, [%1];" : "=f"(a3) : "r"(a_addr + 1584));
            unsigned long long w[8];
            asm("ld.shared.v2.b64 {%0, %1}, [%2];"    : "=l"(w[0]), "=l"(w[1]) : "r"(w_addr));
            asm("ld.shared.v2.b64 {%0, %1}, [%2+16];" : "=l"(w[2]), "=l"(w[3]) : "r"(w_addr));
            asm("ld.shared.v2.b64 {%0, %1}, [%2+32];" : "=l"(w[4]), "=l"(w[5]) : "r"(w_addr));
            asm("ld.shared.v2.b64 {%0, %1}, [%2+48];" : "=l"(w[6]), "=l"(w[7]) : "r"(w_addr));
            unsigned long long aa0 = pk2(a0, a0), aa1 = pk2(a1, a1);
            unsigned long long aa2 = pk2(a2, a2), aa3 = pk2(a3, a3);
#pragma unroll
            for (int j = 0; j < 8; j++) {
                acc[0][j] = fma2(aa0, w[j], acc[0][j]);
                acc[1][j] = fma2(aa1, w[j], acc[1][j]);
                acc[2][j] = fma2(aa2, w[j], acc[2][j]);
                acc[3][j] = fma2(aa3, w[j], acc[3][j]);
            }
            a_addr += 4;
            w_addr += 512;
        }
    }
    __syncthreads();   // all h reads done before overwrite

    // epilogue 1: + b1, relu, write t back into sh
    {
        float bj[16];
#pragma unroll
        for (int j = 0; j < 16; j++) bj[j] = b1[n0 + j];
#pragma unroll
        for (int i = 0; i < 4; i++) {
            float* row = sh + (m0 + i) * H_STRIDE + n0;
#pragma unroll
            for (int j = 0; j < 8; j++) {
                float x, y;
                upk2(acc[i][j], x, y);
                x = fmaxf(x + bj[2 * j], 0.f);
                y = fmaxf(y + bj[2 * j + 1], 0.f);
                *reinterpret_cast<float2*>(row + 2 * j) = make_float2(x, y);
            }
        }
    }
    __syncthreads();

    // ================= GEMM 2: out = t @ W2 + b2 =================
#pragma unroll
    for (int i = 0; i < 4; i++)
#pragma unroll
        for (int j = 0; j < 8; j++) acc[i][j] = 0ULL;

    {
        uint32_t a_addr = sh_u + (uint32_t)(m0 * H_STRIDE) * 4;
        uint32_t w_addr = w2_u;
#pragma unroll 4
        for (int k = 0; k < 128; k++) {
            float a0, a1, a2, a3;
            asm("ld.shared.f32 %0, [%1];" : "=f"(a0) : "r"(a_addr));
            asm("ld.shared.f32 %0, [%1];" : "=f"(a1) : "r"(a_addr + 528));
            asm("ld.shared.f32 %0, [%1];" : "=f"(a2) : "r"(a_addr + 1056));
            asm("ld.shared.f32 %0, [%1];" : "=f"(a3) : "r"(a_addr + 1584));
            unsigned long long w[8];
            asm("ld.shared.v2.b64 {%0, %1}, [%2];"    : "=l"(w[0]), "=l"(w[1]) : "r"(w_addr));
            asm("ld.shared.v2.b64 {%0, %1}, [%2+16];" : "=l"(w[2]), "=l"(w[3]) : "r"(w_addr));
            asm("ld.shared.v2.b64 {%0, %1}, [%2+32];" : "=l"(w[4]), "=l"(w[5]) : "r"(w_addr));
            asm("ld.shared.v2.b64 {%0, %1}, [%2+48];" : "=l"(w[6]), "=l"(w[7]) : "r"(w_addr));
            unsigned long long aa0 = pk2(a0, a0), aa1 = pk2(a1, a1);
            unsigned long long aa2 = pk2(a2, a2), aa3 = pk2(a3, a3);
#pragma unroll
            for (int j = 0; j < 8; j++) {
                acc[0][j] = fma2(aa0, w[j], acc[0][j]);
                acc[1][j] = fma2(aa1, w[j], acc[1][j]);
                acc[2][j] = fma2(aa2, w[j], acc[2][j]);
                acc[3][j] = fma2(aa3, w[j], acc[3][j]);
            }
            a_addr += 4;
            w_addr += 512;
        }
    }

    // epilogue 2: + b2, store to out
    {
        float bj[16];
#pragma unroll
        for (int j = 0; j < 16; j++) bj[j] = b2[n0 + j];
#pragma unroll
        for (int i = 0; i < 4; i++) {
            int m = row_base + m0 + i;
            if (m < N_NODES) {
                float o[16];
#pragma unroll
                for (int j = 0; j < 8; j++) {
                    float x, y;
                    upk2(acc[i][j], x, y);
                    o[2 * j]     = x + bj[2 * j];
                    o[2 * j + 1] = y + bj[2 * j + 1];
                }
                float* orow = out + (size_t)m * D + n0;
#pragma unroll
                for (int j = 0; j < 4; j++) {
                    *reinterpret_cast<float4*>(orow + 4 * j) =
                        make_float4(o[4 * j], o[4 * j + 1], o[4 * j + 2], o[4 * j + 3]);
                }
            }
        }
    }
}

// ---------------------------------------------------------------------------
extern "C" void kernel_launch(void* const* d_in, const int* in_sizes, int n_in,
                              void* d_out, int out_size) {
    const float* feat = (const float*)d_in[0];
    const int*   src  = (const int*)d_in[1];
    const int*   dst  = (const int*)d_in[2];
    const float* eps  = (const float*)d_in[3];
    const float* W1   = (const float*)d_in[4];
    const float* b1   = (const float*)d_in[5];
    const float* W2   = (const float*)d_in[6];
    const float* b2   = (const float*)d_in[7];
    float*       out  = (float*)d_out;

    int n_edges = in_sizes[1];

    // 1) accumulator init with self term
    init_neigh_kernel<<<4096, 256>>>(feat, eps);

    // 2) scatter-add messages
    scatter_kernel<<<2368, 256>>>(feat, src, dst, n_edges);

    // 3) fused MLP (packed f32x2)
    {
        size_t smem_bytes = (size_t)SMEM_FLOATS * sizeof(float);
        cudaFuncSetAttribute(mlp_kernel,
                             cudaFuncAttributeMaxDynamicSharedMemorySize,
                             (int)smem_bytes);
        int blocks = (N_NODES + TILE_M - 1) / TILE_M;
        mlp_kernel<<<blocks, MLP_THREADS, smem_bytes>>>(W1, b1, W2, b2, out);
    }
}

// round 4
// speedup vs baseline: 1.7566x; 1.7566x over previous
#include <cuda_runtime.h>
#include <cuda_bf16.h>
#include <cstdint>

#define N_NODES 100000
#define D 128

// ---------------------------------------------------------------------------
// Device scratch
// ---------------------------------------------------------------------------
__device__ float g_neigh[(size_t)N_NODES * D];   // accumulator (51.2 MB)

// Transposed, padded, split-bf16 weight images: Wt[n][k], row stride 136.
#define ST_ELEM 136
#define ST_W    68        // 32-bit words per row
__device__ __align__(16) uint16_t g_w1hi[D * ST_ELEM];
__device__ __align__(16) uint16_t g_w1lo[D * ST_ELEM];
__device__ __align__(16) uint16_t g_w2hi[D * ST_ELEM];
__device__ __align__(16) uint16_t g_w2lo[D * ST_ELEM];

// ---------------------------------------------------------------------------
// helpers
// ---------------------------------------------------------------------------
__device__ __forceinline__ void mma_bf16(float* c, const uint32_t* a, const uint32_t* b) {
    asm volatile(
        "mma.sync.aligned.m16n8k16.row.col.f32.bf16.bf16.f32 "
        "{%0,%1,%2,%3}, {%4,%5,%6,%7}, {%8,%9}, {%0,%1,%2,%3};"
        : "+f"(c[0]), "+f"(c[1]), "+f"(c[2]), "+f"(c[3])
        : "r"(a[0]), "r"(a[1]), "r"(a[2]), "r"(a[3]), "r"(b[0]), "r"(b[1]));
}

// split two floats into packed hi-bf16x2 / lo-bf16x2 words
__device__ __forceinline__ void split_pack(float x, float y, uint32_t& hp, uint32_t& lp) {
    __nv_bfloat16 xh = __float2bfloat16_rn(x);
    __nv_bfloat16 yh = __float2bfloat16_rn(y);
    __nv_bfloat16 xl = __float2bfloat16_rn(x - __bfloat162float(xh));
    __nv_bfloat16 yl = __float2bfloat16_rn(y - __bfloat162float(yh));
    hp = (uint32_t)__bfloat16_as_ushort(xh) | ((uint32_t)__bfloat16_as_ushort(yh) << 16);
    lp = (uint32_t)__bfloat16_as_ushort(xl) | ((uint32_t)__bfloat16_as_ushort(yl) << 16);
}

// ---------------------------------------------------------------------------
// Kernel 1: g_neigh = (1+eps)*feat
// ---------------------------------------------------------------------------
__global__ void init_neigh_kernel(const float* __restrict__ feat,
                                  const float* __restrict__ epsp) {
    const float e1 = 1.0f + epsp[0];
    size_t total4 = (size_t)N_NODES * D / 4;
    size_t stride = (size_t)gridDim.x * blockDim.x;
    for (size_t i = (size_t)blockIdx.x * blockDim.x + threadIdx.x; i < total4; i += stride) {
        float4 v = reinterpret_cast<const float4*>(feat)[i];
        v.x *= e1; v.y *= e1; v.z *= e1; v.w *= e1;
        reinterpret_cast<float4*>(g_neigh)[i] = v;
    }
}

// ---------------------------------------------------------------------------
// Kernel 2: weight prep. Wt[n][k] = W[k][n], split into bf16 hi/lo, stride 136.
// ---------------------------------------------------------------------------
__global__ void prep_weights_kernel(const float* __restrict__ W1,
                                    const float* __restrict__ W2) {
    int idx = blockIdx.x * blockDim.x + threadIdx.x;
    if (idx >= D * D) return;
    int k = idx >> 7;
    int n = idx & 127;
    int o = n * ST_ELEM + k;
    {
        float w = W1[idx];
        __nv_bfloat16 h = __float2bfloat16_rn(w);
        __nv_bfloat16 l = __float2bfloat16_rn(w - __bfloat162float(h));
        g_w1hi[o] = __bfloat16_as_ushort(h);
        g_w1lo[o] = __bfloat16_as_ushort(l);
    }
    {
        float w = W2[idx];
        __nv_bfloat16 h = __float2bfloat16_rn(w);
        __nv_bfloat16 l = __float2bfloat16_rn(w - __bfloat162float(h));
        g_w2hi[o] = __bfloat16_as_ushort(h);
        g_w2lo[o] = __bfloat16_as_ushort(l);
    }
}

// ---------------------------------------------------------------------------
// Kernel 3: edge scatter (warp/edge, float4 gather + red.global.add.v4)
// ---------------------------------------------------------------------------
__global__ void scatter_kernel(const float* __restrict__ feat,
                               const int* __restrict__ src,
                               const int* __restrict__ dst,
                               int n_edges) {
    long long total = (long long)n_edges * 32;
    long long stride = (long long)gridDim.x * blockDim.x;
    for (long long i = (long long)blockIdx.x * blockDim.x + threadIdx.x;
         i < total; i += stride) {
        int e    = (int)(i >> 5);
        int lane = (int)(i & 31);
        int s = src[e];
        int d = dst[e];
        float4 v = *reinterpret_cast<const float4*>(feat + (size_t)s * D + lane * 4);
        float* p = g_neigh + (size_t)d * D + lane * 4;
        asm volatile("red.global.add.v4.f32 [%0], {%1,%2,%3,%4};"
                     :: "l"(p), "f"(v.x), "f"(v.y), "f"(v.z), "f"(v.w)
                     : "memory");
    }
}

// ---------------------------------------------------------------------------
// Kernel 4: MLP on the legacy HMMA path (mma.sync m16n8k16 bf16, split-bf16).
// Per CTA: 128 rows. 8 warps; warp w owns rows [16w, 16w+16).
// smem (32-bit words): A_hi | A_lo | W_hi | W_lo, each 128*68 words.
// ---------------------------------------------------------------------------
#define TILE_WORDS (128 * ST_W)
#define MLP_SMEM_BYTES (4 * TILE_WORDS * 4)

__global__ __launch_bounds__(256, 1)
void mlp_kernel(const float* __restrict__ b1,
                const float* __restrict__ b2,
                float* __restrict__ out) {
    extern __shared__ uint32_t smem[];
    uint32_t* A_HI = smem;
    uint32_t* A_LO = smem + TILE_WORDS;
    uint32_t* W_HI = smem + 2 * TILE_WORDS;
    uint32_t* W_LO = smem + 3 * TILE_WORDS;

    const int tid = threadIdx.x;
    const int w   = tid >> 5;       // warp 0..7
    const int l   = tid & 31;
    const int g   = l >> 2;         // group row 0..7
    const int t   = l & 3;          // thread-in-group
    const int row_base = blockIdx.x * 128;

    // ---- stage W1 (hi/lo) ----
    {
        const uint4* s1h = reinterpret_cast<const uint4*>(g_w1hi);
        const uint4* s1l = reinterpret_cast<const uint4*>(g_w1lo);
        uint4* dh = reinterpret_cast<uint4*>(W_HI);
        uint4* dl = reinterpret_cast<uint4*>(W_LO);
        for (int i = tid; i < TILE_WORDS / 4; i += 256) { dh[i] = s1h[i]; dl[i] = s1l[i]; }
    }

    // ---- stage A: h rows -> split-bf16 tiles ----
    for (int i = tid; i < 128 * 32; i += 256) {
        int r  = i >> 5;
        int c4 = (i & 31) * 4;                // float column
        int m  = row_base + r;
        float4 v = (m < N_NODES)
                 ? *reinterpret_cast<const float4*>(g_neigh + (size_t)m * D + c4)
                 : make_float4(0.f, 0.f, 0.f, 0.f);
        uint32_t h0, l0, h1, l1;
        split_pack(v.x, v.y, h0, l0);
        split_pack(v.z, v.w, h1, l1);
        int word = r * ST_W + (c4 >> 1);
        A_HI[word] = h0; A_HI[word + 1] = h1;
        A_LO[word] = l0; A_LO[word + 1] = l1;
    }
    __syncthreads();

    float acc[16][4];
#pragma unroll
    for (int nt = 0; nt < 16; nt++)
#pragma unroll
        for (int j = 0; j < 4; j++) acc[nt][j] = 0.f;

    const int ar0 = (w * 16 + g) * ST_W;      // A word base, rows r and r+8
    const int ar1 = (w * 16 + g + 8) * ST_W;

    // ================= GEMM 1 =================
#pragma unroll
    for (int kc = 0; kc < 8; kc++) {
        const int kw = kc * 8 + t;            // word column within row
        uint32_t ah[4], al[4];
        ah[0] = A_HI[ar0 + kw];     ah[1] = A_HI[ar1 + kw];
        ah[2] = A_HI[ar0 + kw + 4]; ah[3] = A_HI[ar1 + kw + 4];
        al[0] = A_LO[ar0 + kw];     al[1] = A_LO[ar1 + kw];
        al[2] = A_LO[ar0 + kw + 4]; al[3] = A_LO[ar1 + kw + 4];
#pragma unroll
        for (int nt = 0; nt < 16; nt++) {
            const int bb = (nt * 8 + g) * ST_W + kw;
            uint32_t bh[2] = { W_HI[bb], W_HI[bb + 4] };
            uint32_t bl[2] = { W_LO[bb], W_LO[bb + 4] };
            mma_bf16(acc[nt], ah, bh);
            mma_bf16(acc[nt], ah, bl);
            mma_bf16(acc[nt], al, bh);
        }
    }
    __syncthreads();   // everyone done with W1 before overwrite

    // ---- epilogue 1: relu(+b1), split back into A tiles (own rows only) ----
#pragma unroll
    for (int nt = 0; nt < 16; nt++) {
        const int n = nt * 8 + 2 * t;
        const float bx = __ldg(b1 + n);
        const float by = __ldg(b1 + n + 1);
        float x0 = fmaxf(acc[nt][0] + bx, 0.f);
        float y0 = fmaxf(acc[nt][1] + by, 0.f);
        float x1 = fmaxf(acc[nt][2] + bx, 0.f);
        float y1 = fmaxf(acc[nt][3] + by, 0.f);
        uint32_t hp, lp;
        const int word0 = (w * 16 + g) * ST_W + nt * 4 + t;
        const int word1 = (w * 16 + g + 8) * ST_W + nt * 4 + t;
        split_pack(x0, y0, hp, lp);
        A_HI[word0] = hp; A_LO[word0] = lp;
        split_pack(x1, y1, hp, lp);
        A_HI[word1] = hp; A_LO[word1] = lp;
#pragma unroll
        for (int j = 0; j < 4; j++) acc[nt][j] = 0.f;
    }

    // ---- stage W2 ----
    {
        const uint4* s2h = reinterpret_cast<const uint4*>(g_w2hi);
        const uint4* s2l = reinterpret_cast<const uint4*>(g_w2lo);
        uint4* dh = reinterpret_cast<uint4*>(W_HI);
        uint4* dl = reinterpret_cast<uint4*>(W_LO);
        for (int i = tid; i < TILE_WORDS / 4; i += 256) { dh[i] = s2h[i]; dl[i] = s2l[i]; }
    }
    __syncthreads();

    // ================= GEMM 2 =================
#pragma unroll
    for (int kc = 0; kc < 8; kc++) {
        const int kw = kc * 8 + t;
        uint32_t ah[4], al[4];
        ah[0] = A_HI[ar0 + kw];     ah[1] = A_HI[ar1 + kw];
        ah[2] = A_HI[ar0 + kw + 4]; ah[3] = A_HI[ar1 + kw + 4];
        al[0] = A_LO[ar0 + kw];     al[1] = A_LO[ar1 + kw];
        al[2] = A_LO[ar0 + kw + 4]; al[3] = A_LO[ar1 + kw + 4];
#pragma unroll
        for (int nt = 0; nt < 16; nt++) {
            const int bb = (nt * 8 + g) * ST_W + kw;
            uint32_t bh[2] = { W_HI[bb], W_HI[bb + 4] };
            uint32_t bl[2] = { W_LO[bb], W_LO[bb + 4] };
            mma_bf16(acc[nt], ah, bh);
            mma_bf16(acc[nt], ah, bl);
            mma_bf16(acc[nt], al, bh);
        }
    }

    // ---- epilogue 2: +b2, store ----
    {
        const int m0 = row_base + w * 16 + g;
        const int m1 = m0 + 8;
#pragma unroll
        for (int nt = 0; nt < 16; nt++) {
            const int n = nt * 8 + 2 * t;
            const float bx = __ldg(b2 + n);
            const float by = __ldg(b2 + n + 1);
            if (m0 < N_NODES)
                *reinterpret_cast<float2*>(out + (size_t)m0 * D + n) =
                    make_float2(acc[nt][0] + bx, acc[nt][1] + by);
            if (m1 < N_NODES)
                *reinterpret_cast<float2*>(out + (size_t)m1 * D + n) =
                    make_float2(acc[nt][2] + bx, acc[nt][3] + by);
        }
    }
}

// ---------------------------------------------------------------------------
extern "C" void kernel_launch(void* const* d_in, const int* in_sizes, int n_in,
                              void* d_out, int out_size) {
    const float* feat = (const float*)d_in[0];
    const int*   src  = (const int*)d_in[1];
    const int*   dst  = (const int*)d_in[2];
    const float* eps  = (const float*)d_in[3];
    const float* W1   = (const float*)d_in[4];
    const float* b1   = (const float*)d_in[5];
    const float* W2   = (const float*)d_in[6];
    const float* b2   = (const float*)d_in[7];
    float*       out  = (float*)d_out;

    int n_edges = in_sizes[1];

    // 1) accumulator init with self term
    init_neigh_kernel<<<4096, 256>>>(feat, eps);

    // 2) weight prep (transposed split-bf16 images)
    prep_weights_kernel<<<(D * D + 255) / 256, 256>>>(W1, W2);

    // 3) edge scatter-add
    scatter_kernel<<<2368, 256>>>(feat, src, dst, n_edges);

    // 4) HMMA MLP
    cudaFuncSetAttribute(mlp_kernel, cudaFuncAttributeMaxDynamicSharedMemorySize,
                         MLP_SMEM_BYTES);
    int blocks = (N_NODES + 127) / 128;
    mlp_kernel<<<blocks, 256, MLP_SMEM_BYTES>>>(b1, b2, out);
}

// round 5
// speedup vs baseline: 2.8045x; 1.5966x over previous
#include <cuda_runtime.h>
#include <cuda_bf16.h>
#include <cstdint>

#define N_NODES 100000
#define N_EDGES_MAX 3200000
#define D 128

// ---------------------------------------------------------------------------
// Device scratch (static; no runtime alloc)
// ---------------------------------------------------------------------------
__device__ float    g_neigh[(size_t)N_NODES * D];      // (1+eps)feat + sum  (51.2MB)
__device__ int      g_cnt[N_NODES];                     // in-degree histogram
__device__ int      g_off[N_NODES + 1];                 // CSR offsets (by dst)
__device__ int      g_cur[N_NODES];                     // running fill cursor
__device__ int      g_srcs[N_EDGES_MAX];                // src ids sorted by dst bin
__device__ int      g_blksum[128];                      // scan partials
__device__ int      g_blkoff[128];

// Transposed, padded, split-bf16 weight images: Wt[n][k], row stride 136 elems.
#define ST_ELEM 136
#define ST_W    68
__device__ __align__(16) uint16_t g_w1hi[D * ST_ELEM];
__device__ __align__(16) uint16_t g_w1lo[D * ST_ELEM];
__device__ __align__(16) uint16_t g_w2hi[D * ST_ELEM];
__device__ __align__(16) uint16_t g_w2lo[D * ST_ELEM];

#define SCAN_BLK 1024
#define N_SCAN_BLKS ((N_NODES + SCAN_BLK - 1) / SCAN_BLK)   // 98

// ---------------------------------------------------------------------------
// helpers
// ---------------------------------------------------------------------------
__device__ __forceinline__ void mma_bf16(float* c, const uint32_t* a, const uint32_t* b) {
    asm volatile(
        "mma.sync.aligned.m16n8k16.row.col.f32.bf16.bf16.f32 "
        "{%0,%1,%2,%3}, {%4,%5,%6,%7}, {%8,%9}, {%0,%1,%2,%3};"
        : "+f"(c[0]), "+f"(c[1]), "+f"(c[2]), "+f"(c[3])
        : "r"(a[0]), "r"(a[1]), "r"(a[2]), "r"(a[3]), "r"(b[0]), "r"(b[1]));
}

__device__ __forceinline__ void split_pack(float x, float y, uint32_t& hp, uint32_t& lp) {
    __nv_bfloat16 xh = __float2bfloat16_rn(x);
    __nv_bfloat16 yh = __float2bfloat16_rn(y);
    __nv_bfloat16 xl = __float2bfloat16_rn(x - __bfloat162float(xh));
    __nv_bfloat16 yl = __float2bfloat16_rn(y - __bfloat162float(yh));
    hp = (uint32_t)__bfloat16_as_ushort(xh) | ((uint32_t)__bfloat16_as_ushort(yh) << 16);
    lp = (uint32_t)__bfloat16_as_ushort(xl) | ((uint32_t)__bfloat16_as_ushort(yl) << 16);
}

// ---------------------------------------------------------------------------
// Binning pipeline
// ---------------------------------------------------------------------------
__global__ void zero_cnt_kernel() {
    int i = blockIdx.x * blockDim.x + threadIdx.x;
    if (i < N_NODES) g_cnt[i] = 0;
}

__global__ void hist_kernel(const int* __restrict__ dst, int n_edges) {
    int i = blockIdx.x * blockDim.x + threadIdx.x;
    if (i < n_edges) atomicAdd(&g_cnt[dst[i]], 1);
}

// per-block sums of g_cnt (1024-elem blocks)
__global__ void scan_block_kernel() {
    __shared__ int s[SCAN_BLK];
    int t = threadIdx.x;
    int i = blockIdx.x * SCAN_BLK + t;
    s[t] = (i < N_NODES) ? g_cnt[i] : 0;
    __syncthreads();
    for (int off = SCAN_BLK / 2; off > 0; off >>= 1) {
        if (t < off) s[t] += s[t + off];
        __syncthreads();
    }
    if (t == 0) g_blksum[blockIdx.x] = s[0];
}

// exclusive scan of 98 block sums (single block)
__global__ void scan_top_kernel() {
    __shared__ int s[128];
    int t = threadIdx.x;
    s[t] = (t < N_SCAN_BLKS) ? g_blksum[t] : 0;
    __syncthreads();
    // simple serial-ish scan by thread 0 (98 elems, trivial)
    if (t == 0) {
        int run = 0;
        for (int b = 0; b < N_SCAN_BLKS; b++) {
            g_blkoff[b] = run;
            run += s[b];
        }
        g_off[N_NODES] = run;
    }
}

// block-wide exclusive scan -> final offsets + cursors
__global__ void scan_final_kernel() {
    __shared__ int s[SCAN_BLK];
    int t = threadIdx.x;
    int i = blockIdx.x * SCAN_BLK + t;
    int v = (i < N_NODES) ? g_cnt[i] : 0;
    s[t] = v;
    __syncthreads();
    for (int off = 1; off < SCAN_BLK; off <<= 1) {
        int x = (t >= off) ? s[t - off] : 0;
        __syncthreads();
        s[t] += x;
        __syncthreads();
    }
    if (i < N_NODES) {
        int excl = s[t] - v + g_blkoff[blockIdx.x];
        g_off[i] = excl;
        g_cur[i] = excl;
    }
}

__global__ void fill_kernel(const int* __restrict__ src,
                            const int* __restrict__ dst, int n_edges) {
    int i = blockIdx.x * blockDim.x + threadIdx.x;
    if (i < n_edges) {
        int pos = atomicAdd(&g_cur[dst[i]], 1);
        g_srcs[pos] = src[i];
    }
}

// ---------------------------------------------------------------------------
// Gather-reduce: warp per node. g_neigh[v] = (1+eps)*feat[v] + sum feat[srcs]
// ---------------------------------------------------------------------------
__global__ __launch_bounds__(256)
void gather_kernel(const float* __restrict__ feat,
                   const float* __restrict__ epsp) {
    const int warp = (blockIdx.x * blockDim.x + threadIdx.x) >> 5;
    const int lane = threadIdx.x & 31;
    if (warp >= N_NODES) return;
    const int v = warp;
    const float e1 = 1.0f + epsp[0];

    const float4* f4 = reinterpret_cast<const float4*>(feat);
    float4 a = f4[(size_t)v * 32 + lane];
    float4 acc = make_float4(a.x * e1, a.y * e1, a.z * e1, a.w * e1);

    const int beg = g_off[v];
    const int end = g_off[v + 1];
    for (int e = beg; e < end; e += 32) {
        int cnt = end - e;
        if (cnt > 32) cnt = 32;
        int s = (lane < cnt) ? g_srcs[e + lane] : 0;
        if (cnt == 32) {
#pragma unroll
            for (int j = 0; j < 32; j++) {
                int sj = __shfl_sync(0xffffffffu, s, j);
                float4 m = f4[(size_t)sj * 32 + lane];
                acc.x += m.x; acc.y += m.y; acc.z += m.z; acc.w += m.w;
            }
        } else {
            for (int j = 0; j < cnt; j++) {
                int sj = __shfl_sync(0xffffffffu, s, j);
                float4 m = f4[(size_t)sj * 32 + lane];
                acc.x += m.x; acc.y += m.y; acc.z += m.z; acc.w += m.w;
            }
        }
    }
    reinterpret_cast<float4*>(g_neigh)[(size_t)v * 32 + lane] = acc;
}

// ---------------------------------------------------------------------------
// Weight prep: Wt[n][k] = W[k][n], split bf16 hi/lo, stride 136
// ---------------------------------------------------------------------------
__global__ void prep_weights_kernel(const float* __restrict__ W1,
                                    const float* __restrict__ W2) {
    int idx = blockIdx.x * blockDim.x + threadIdx.x;
    if (idx >= D * D) return;
    int k = idx >> 7;
    int n = idx & 127;
    int o = n * ST_ELEM + k;
    {
        float w = W1[idx];
        __nv_bfloat16 h = __float2bfloat16_rn(w);
        __nv_bfloat16 l = __float2bfloat16_rn(w - __bfloat162float(h));
        g_w1hi[o] = __bfloat16_as_ushort(h);
        g_w1lo[o] = __bfloat16_as_ushort(l);
    }
    {
        float w = W2[idx];
        __nv_bfloat16 h = __float2bfloat16_rn(w);
        __nv_bfloat16 l = __float2bfloat16_rn(w - __bfloat162float(h));
        g_w2hi[o] = __bfloat16_as_ushort(h);
        g_w2lo[o] = __bfloat16_as_ushort(l);
    }
}

// ---------------------------------------------------------------------------
// MLP (HMMA split-bf16). 512 threads / 16 warps per CTA, 128 rows per CTA.
// Warp (wr, half): rows [16*wr, 16*wr+16), cols [64*half, 64*half+64).
// ---------------------------------------------------------------------------
#define TILE_WORDS (128 * ST_W)
#define MLP_SMEM_BYTES (4 * TILE_WORDS * 4)

__global__ __launch_bounds__(512, 1)
void mlp_kernel(const float* __restrict__ b1,
                const float* __restrict__ b2,
                float* __restrict__ out) {
    extern __shared__ uint32_t smem[];
    uint32_t* A_HI = smem;
    uint32_t* A_LO = smem + TILE_WORDS;
    uint32_t* W_HI = smem + 2 * TILE_WORDS;
    uint32_t* W_LO = smem + 3 * TILE_WORDS;

    const int tid  = threadIdx.x;
    const int wid  = tid >> 5;        // 0..15
    const int wr   = wid & 7;         // row group
    const int half = wid >> 3;        // n half
    const int l    = tid & 31;
    const int g    = l >> 2;
    const int t    = l & 3;
    const int row_base = blockIdx.x * 128;

    // ---- stage W1 ----
    {
        const uint4* s1h = reinterpret_cast<const uint4*>(g_w1hi);
        const uint4* s1l = reinterpret_cast<const uint4*>(g_w1lo);
        uint4* dh = reinterpret_cast<uint4*>(W_HI);
        uint4* dl = reinterpret_cast<uint4*>(W_LO);
        for (int i = tid; i < TILE_WORDS / 4; i += 512) { dh[i] = s1h[i]; dl[i] = s1l[i]; }
    }

    // ---- stage A ----
    for (int i = tid; i < 128 * 32; i += 512) {
        int r  = i >> 5;
        int c4 = (i & 31) * 4;
        int m  = row_base + r;
        float4 v = (m < N_NODES)
                 ? *reinterpret_cast<const float4*>(g_neigh + (size_t)m * D + c4)
                 : make_float4(0.f, 0.f, 0.f, 0.f);
        uint32_t h0, l0, h1, l1;
        split_pack(v.x, v.y, h0, l0);
        split_pack(v.z, v.w, h1, l1);
        int word = r * ST_W + (c4 >> 1);
        A_HI[word] = h0; A_HI[word + 1] = h1;
        A_LO[word] = l0; A_LO[word + 1] = l1;
    }
    __syncthreads();

    float acc[8][4];
#pragma unroll
    for (int nt = 0; nt < 8; nt++)
#pragma unroll
        for (int j = 0; j < 4; j++) acc[nt][j] = 0.f;

    const int ar0 = (wr * 16 + g) * ST_W;
    const int ar1 = (wr * 16 + g + 8) * ST_W;

    // ================= GEMM 1 =================
#pragma unroll
    for (int kc = 0; kc < 8; kc++) {
        const int kw = kc * 8 + t;
        uint32_t ah[4], al[4];
        ah[0] = A_HI[ar0 + kw];     ah[1] = A_HI[ar1 + kw];
        ah[2] = A_HI[ar0 + kw + 4]; ah[3] = A_HI[ar1 + kw + 4];
        al[0] = A_LO[ar0 + kw];     al[1] = A_LO[ar1 + kw];
        al[2] = A_LO[ar0 + kw + 4]; al[3] = A_LO[ar1 + kw + 4];
#pragma unroll
        for (int nt = 0; nt < 8; nt++) {
            const int bb = ((half * 64 + nt * 8 + g)) * ST_W + kw;
            uint32_t bh[2] = { W_HI[bb], W_HI[bb + 4] };
            uint32_t bl[2] = { W_LO[bb], W_LO[bb + 4] };
            mma_bf16(acc[nt], ah, bh);
            mma_bf16(acc[nt], ah, bl);
            mma_bf16(acc[nt], al, bh);
        }
    }
    __syncthreads();

    // ---- epilogue 1: relu(+b1) -> back into A tiles ----
#pragma unroll
    for (int nt = 0; nt < 8; nt++) {
        const int n = half * 64 + nt * 8 + 2 * t;
        const float bx = __ldg(b1 + n);
        const float by = __ldg(b1 + n + 1);
        float x0 = fmaxf(acc[nt][0] + bx, 0.f);
        float y0 = fmaxf(acc[nt][1] + by, 0.f);
        float x1 = fmaxf(acc[nt][2] + bx, 0.f);
        float y1 = fmaxf(acc[nt][3] + by, 0.f);
        uint32_t hp, lp;
        const int word0 = (wr * 16 + g) * ST_W + (n >> 1);
        const int word1 = (wr * 16 + g + 8) * ST_W + (n >> 1);
        split_pack(x0, y0, hp, lp);
        A_HI[word0] = hp; A_LO[word0] = lp;
        split_pack(x1, y1, hp, lp);
        A_HI[word1] = hp; A_LO[word1] = lp;
#pragma unroll
        for (int j = 0; j < 4; j++) acc[nt][j] = 0.f;
    }

    // ---- stage W2 ----
    {
        const uint4* s2h = reinterpret_cast<const uint4*>(g_w2hi);
        const uint4* s2l = reinterpret_cast<const uint4*>(g_w2lo);
        uint4* dh = reinterpret_cast<uint4*>(W_HI);
        uint4* dl = reinterpret_cast<uint4*>(W_LO);
        for (int i = tid; i < TILE_WORDS / 4; i += 512) { dh[i] = s2h[i]; dl[i] = s2l[i]; }
    }
    __syncthreads();

    // ================= GEMM 2 =================
#pragma unroll
    for (int kc = 0; kc < 8; kc++) {
        const int kw = kc * 8 + t;
        uint32_t ah[4], al[4];
        ah[0] = A_HI[ar0 + kw];     ah[1] = A_HI[ar1 + kw];
        ah[2] = A_HI[ar0 + kw + 4]; ah[3] = A_HI[ar1 + kw + 4];
        al[0] = A_LO[ar0 + kw];     al[1] = A_LO[ar1 + kw];
        al[2] = A_LO[ar0 + kw + 4]; al[3] = A_LO[ar1 + kw + 4];
#pragma unroll
        for (int nt = 0; nt < 8; nt++) {
            const int bb = ((half * 64 + nt * 8 + g)) * ST_W + kw;
            uint32_t bh[2] = { W_HI[bb], W_HI[bb + 4] };
            uint32_t bl[2] = { W_LO[bb], W_LO[bb + 4] };
            mma_bf16(acc[nt], ah, bh);
            mma_bf16(acc[nt], ah, bl);
            mma_bf16(acc[nt], al, bh);
        }
    }

    // ---- epilogue 2: +b2, store ----
    {
        const int m0 = row_base + wr * 16 + g;
        const int m1 = m0 + 8;
#pragma unroll
        for (int nt = 0; nt < 8; nt++) {
            const int n = half * 64 + nt * 8 + 2 * t;
            const float bx = __ldg(b2 + n);
            const float by = __ldg(b2 + n + 1);
            if (m0 < N_NODES)
                *reinterpret_cast<float2*>(out + (size_t)m0 * D + n) =
                    make_float2(acc[nt][0] + bx, acc[nt][1] + by);
            if (m1 < N_NODES)
                *reinterpret_cast<float2*>(out + (size_t)m1 * D + n) =
                    make_float2(acc[nt][2] + bx, acc[nt][3] + by);
        }
    }
}

// ---------------------------------------------------------------------------
extern "C" void kernel_launch(void* const* d_in, const int* in_sizes, int n_in,
                              void* d_out, int out_size) {
    const float* feat = (const float*)d_in[0];
    const int*   src  = (const int*)d_in[1];
    const int*   dst  = (const int*)d_in[2];
    const float* eps  = (const float*)d_in[3];
    const float* W1   = (const float*)d_in[4];
    const float* b1   = (const float*)d_in[5];
    const float* W2   = (const float*)d_in[6];
    const float* b2   = (const float*)d_in[7];
    float*       out  = (float*)d_out;

    int n_edges = in_sizes[1];
    int eblocks = (n_edges + 255) / 256;

    // ---- binning ----
    zero_cnt_kernel<<<(N_NODES + 255) / 256, 256>>>();
    hist_kernel<<<eblocks, 256>>>(dst, n_edges);
    scan_block_kernel<<<N_SCAN_BLKS, SCAN_BLK>>>();
    scan_top_kernel<<<1, 128>>>();
    scan_final_kernel<<<N_SCAN_BLKS, SCAN_BLK>>>();
    fill_kernel<<<eblocks, 256>>>(src, dst, n_edges);

    // ---- gather-reduce (includes (1+eps)*feat self term) ----
    gather_kernel<<<(N_NODES * 32 + 255) / 256, 256>>>(feat, eps);

    // ---- weights + MLP ----
    prep_weights_kernel<<<(D * D + 255) / 256, 256>>>(W1, W2);
    cudaFuncSetAttribute(mlp_kernel, cudaFuncAttributeMaxDynamicSharedMemorySize,
                         MLP_SMEM_BYTES);
    int blocks = (N_NODES + 127) / 128;
    mlp_kernel<<<blocks, 512, MLP_SMEM_BYTES>>>(b1, b2, out);
}